// round 2
// baseline (speedup 1.0000x reference)
#include <cuda_runtime.h>

#define NUM_USERS 100000
#define NUM_ITEMS 50000
#define N_NODES   150000
#define C         64
#define NNZ       2400000
#define BATCH     8192
#define NEG_SLOPE 0.1f
#define EPS       1e-12f

// Propagation state
__device__ float g_bufA[(size_t)N_NODES * C];
__device__ float g_bufB[(size_t)N_NODES * C];
__device__ float g_acc [(size_t)N_NODES * C];

// CSR scratch (rebuilt every call — determinism up to atomic ordering)
__device__ int   g_rowptr[N_NODES + 1];
__device__ int   g_off   [N_NODES];
__device__ int   g_csr_col[NNZ];
__device__ float g_csr_val[NNZ];

__device__ __forceinline__ float lrelu(float x) {
    return x >= 0.0f ? x : NEG_SLOPE * x;
}

__device__ __forceinline__ float warp_sum(float s) {
#pragma unroll
    for (int o = 16; o; o >>= 1) s += __shfl_xor_sync(0xffffffffu, s, o);
    return s;
}

// ---------------- CSR build ----------------

__global__ __launch_bounds__(256) void k_zero_counts() {
    int i = blockIdx.x * blockDim.x + threadIdx.x;
    if (i <= N_NODES) g_rowptr[i] = 0;
}

__global__ __launch_bounds__(256) void k_hist(const int* __restrict__ erow) {
    int e = blockIdx.x * blockDim.x + threadIdx.x;
    if (e < NNZ) atomicAdd(&g_rowptr[erow[e] + 1], 1);
}

// Single-block scan over N_NODES+1 entries. After this, g_rowptr[i] = start
// of row i's segment (g_rowptr[N_NODES] == NNZ), and g_off mirrors the starts.
__global__ __launch_bounds__(1024) void k_scan() {
    __shared__ int sums[1024];
    const int NTOT = N_NODES + 1;
    int t = threadIdx.x;
    int per = (NTOT + 1023) / 1024;
    int beg = t * per;
    int end = min(beg + per, NTOT);

    int run = 0;
    for (int i = beg; i < end; ++i) { run += g_rowptr[i]; g_rowptr[i] = run; }
    sums[t] = run;
    __syncthreads();
#pragma unroll
    for (int off = 1; off < 1024; off <<= 1) {
        int v = (t >= off) ? sums[t - off] : 0;
        __syncthreads();
        sums[t] += v;
        __syncthreads();
    }
    int offset = (t > 0) ? sums[t - 1] : 0;
    for (int i = beg; i < end; ++i) {
        int v = g_rowptr[i] + offset;
        g_rowptr[i] = v;
        if (i < N_NODES) g_off[i] = v;
    }
}

__global__ __launch_bounds__(256) void k_scatter(const int* __restrict__ erow,
                                                 const int* __restrict__ ecol,
                                                 const float* __restrict__ eval) {
    int e = blockIdx.x * blockDim.x + threadIdx.x;
    if (e >= NNZ) return;
    int r = erow[e];
    int pos = atomicAdd(&g_off[r], 1);
    g_csr_col[pos] = ecol[e];
    g_csr_val[pos] = eval[e];
}

// ---------------- init ----------------

__global__ __launch_bounds__(256) void k_init(const float* __restrict__ up,
                                              const float* __restrict__ ip) {
    int row = blockIdx.x * (blockDim.x >> 5) + (threadIdx.x >> 5);
    if (row >= N_NODES) return;
    int lane = threadIdx.x & 31;

    const float* src = (row < NUM_USERS)
                           ? (up + (size_t)row * C)
                           : (ip + (size_t)(row - NUM_USERS) * C);
    float2 v = reinterpret_cast<const float2*>(src)[lane];
    v.x = lrelu(v.x);
    v.y = lrelu(v.y);
    float s = warp_sum(v.x * v.x + v.y * v.y);
    float inv = 1.0f / fmaxf(sqrtf(s), EPS);
    v.x *= inv; v.y *= inv;

    size_t idx = (size_t)row * 32 + lane;
    reinterpret_cast<float2*>(g_bufA)[idx] = v;
    reinterpret_cast<float2*>(g_acc)[idx]  = v;
}

// ---------------- fused layer: gather-SpMM + lrelu + l2norm + acc ----------------
// One warp per row. Lanes hold 2 features each (float2).

__global__ __launch_bounds__(256) void k_layer(int flip) {
    const float* __restrict__ p  = flip ? g_bufB : g_bufA;
    float* __restrict__       pn = flip ? g_bufA : g_bufB;

    int row = blockIdx.x * (blockDim.x >> 5) + (threadIdx.x >> 5);
    if (row >= N_NODES) return;
    int lane = threadIdx.x & 31;

    int start = g_rowptr[row];
    int end   = g_rowptr[row + 1];

    const float2* __restrict__ p2 = reinterpret_cast<const float2*>(p);
    float2 s = make_float2(0.0f, 0.0f);

    for (int i = start; i < end; i += 32) {
        int n = min(32, end - i);
        int   c = 0;
        float v = 0.0f;
        if (lane < n) {
            c = g_csr_col[i + lane];
            v = g_csr_val[i + lane];
        }
        for (int j = 0; j < n; ++j) {
            int   cj = __shfl_sync(0xffffffffu, c, j);
            float vj = __shfl_sync(0xffffffffu, v, j);
            float2 x = __ldg(p2 + (size_t)cj * 32 + lane);
            s.x = fmaf(vj, x.x, s.x);
            s.y = fmaf(vj, x.y, s.y);
        }
    }

    s.x = lrelu(s.x);
    s.y = lrelu(s.y);
    float nrm = warp_sum(s.x * s.x + s.y * s.y);
    float inv = 1.0f / fmaxf(sqrtf(nrm), EPS);
    s.x *= inv; s.y *= inv;

    size_t idx = (size_t)row * 32 + lane;
    reinterpret_cast<float2*>(pn)[idx] = s;
    float2 a = reinterpret_cast<float2*>(g_acc)[idx];
    a.x += s.x; a.y += s.y;
    reinterpret_cast<float2*>(g_acc)[idx] = a;
}

// ---------------- scoring ----------------

__global__ __launch_bounds__(256) void k_score(const int* __restrict__ users,
                                               const int* __restrict__ adj,
                                               const int* __restrict__ weak,
                                               const int* __restrict__ strong,
                                               float* __restrict__ out) {
    int b = blockIdx.x * (blockDim.x >> 5) + (threadIdx.x >> 5);
    if (b >= BATCH) return;
    int lane = threadIdx.x & 31;

    const float2* acc2 = reinterpret_cast<const float2*>(g_acc);
    int u  = users[b];
    int i0 = NUM_USERS + adj[b];
    int i1 = NUM_USERS + weak[b];
    int i2 = NUM_USERS + strong[b];

    float2 uv = acc2[(size_t)u  * 32 + lane];
    float2 a0 = acc2[(size_t)i0 * 32 + lane];
    float2 a1 = acc2[(size_t)i1 * 32 + lane];
    float2 a2 = acc2[(size_t)i2 * 32 + lane];

    float d0 = warp_sum(uv.x * a0.x + uv.y * a0.y);
    float d1 = warp_sum(uv.x * a1.x + uv.y * a1.y);
    float d2 = warp_sum(uv.x * a2.x + uv.y * a2.y);

    if (lane == 0) {
        out[0 * BATCH + b] = 1.0f / (1.0f + expf(-d0 * (1.0f / 16.0f)));
        out[1 * BATCH + b] = 1.0f / (1.0f + expf(-d1 * (1.0f / 16.0f)));
        out[2 * BATCH + b] = 1.0f / (1.0f + expf(-d2 * (1.0f / 16.0f)));
    }
}

extern "C" void kernel_launch(void* const* d_in, const int* in_sizes, int n_in,
                              void* d_out, int out_size) {
    const int*   users  = (const int*)d_in[0];
    const int*   adj    = (const int*)d_in[1];
    const int*   weak   = (const int*)d_in[2];
    const int*   strong = (const int*)d_in[3];
    const int*   erow   = (const int*)d_in[4];
    const int*   ecol   = (const int*)d_in[5];
    const float* eval   = (const float*)d_in[6];
    const float* up     = (const float*)d_in[7];
    const float* ip     = (const float*)d_in[8];
    float* out = (float*)d_out;

    const int ROWS_BLOCKS = (N_NODES + 7) / 8;          // 8 warps/block
    const int EDGE_BLOCKS = (NNZ + 255) / 256;

    // CSR build
    k_zero_counts<<<(N_NODES + 256) / 256, 256>>>();
    k_hist<<<EDGE_BLOCKS, 256>>>(erow);
    k_scan<<<1, 1024>>>();
    k_scatter<<<EDGE_BLOCKS, 256>>>(erow, ecol, eval);

    // init normalized preferences
    k_init<<<ROWS_BLOCKS, 256>>>(up, ip);

    // 3 fused propagation layers
    int flip = 0;
    for (int layer = 0; layer < 3; ++layer) {
        k_layer<<<ROWS_BLOCKS, 256>>>(flip);
        flip ^= 1;
    }

    k_score<<<(BATCH + 7) / 8, 256>>>(users, adj, weak, strong, out);
}